// round 10
// baseline (speedup 1.0000x reference)
#include <cuda_runtime.h>

#define NQ       12
#define DIM      4096            // 2^12
#define NLAYERS  6
#define NGATES   (NLAYERS * NQ)  // 72
#define NPASS    (NLAYERS * 3)   // 18 fused passes
#define THREADS  128
#define APT      (DIM / THREADS) // 32 amplitudes per thread

typedef unsigned long long ull;

// Bank-conflict-avoiding layout: amplitude p lives at sAmp[SWZ(p)]. GF(2)-linear.
#define SWZ(p) ((p) ^ (((p) >> 4) & 0xFu))

// GF(2) matrices of the CNOT-chain map per layer (verified: rowA.colB = I,
// leading bit of cCOLB[l][q] is q). cROWA[l][j] = row j of T^l; cCOLB = col of T^-l.
__constant__ unsigned cROWA[NLAYERS + 1][NQ] = {
    {0x001,0x002,0x004,0x008,0x010,0x020,0x040,0x080,0x100,0x200,0x400,0x800},
    {0xFFF,0xFFE,0xFFC,0xFF8,0xFF0,0xFE0,0xFC0,0xF80,0xF00,0xE00,0xC00,0x800},
    {0x555,0xAAA,0x554,0xAA8,0x550,0xAA0,0x540,0xA80,0x500,0xA00,0x400,0x800},
    {0x333,0x666,0xCCC,0x998,0x330,0x660,0xCC0,0x980,0x300,0x600,0xC00,0x800},
    {0x111,0x222,0x444,0x888,0x110,0x220,0x440,0x880,0x100,0x200,0x400,0x800},
    {0xF0F,0xE1E,0xC3C,0x878,0x0F0,0x1E0,0x3C0,0x780,0xF00,0xE00,0xC00,0x800},
    {0x505,0xA0A,0x414,0x828,0x050,0x0A0,0x140,0x280,0x500,0xA00,0x400,0x800},
};
__constant__ unsigned cCOLB[NLAYERS][NQ] = {
    {0x001,0x002,0x004,0x008,0x010,0x020,0x040,0x080,0x100,0x200,0x400,0x800},
    {0x001,0x003,0x006,0x00C,0x018,0x030,0x060,0x0C0,0x180,0x300,0x600,0xC00},
    {0x001,0x002,0x005,0x00A,0x014,0x028,0x050,0x0A0,0x140,0x280,0x500,0xA00},
    {0x001,0x003,0x007,0x00F,0x01E,0x03C,0x078,0x0F0,0x1E0,0x3C0,0x780,0xF00},
    {0x001,0x002,0x004,0x008,0x011,0x022,0x044,0x088,0x110,0x220,0x440,0x880},
    {0x001,0x003,0x006,0x00C,0x019,0x033,0x066,0x0CC,0x198,0x330,0x660,0xCC0},
};

// ---- packed f32x2 primitives ----
__device__ __forceinline__ ull f2mul(ull a, ull b) {
    ull d; asm("mul.rn.f32x2 %0, %1, %2;" : "=l"(d) : "l"(a), "l"(b)); return d;
}
__device__ __forceinline__ ull f2fma(ull a, ull b, ull c) {
    ull d; asm("fma.rn.f32x2 %0, %1, %2, %3;" : "=l"(d) : "l"(a), "l"(b), "l"(c)); return d;
}
__device__ __forceinline__ ull f2swap(ull v) {  // (re,im) -> (im,re)
    ull d;
    asm("{\n\t.reg .b32 lo, hi;\n\tmov.b64 {lo, hi}, %1;\n\tmov.b64 %0, {hi, lo};\n\t}"
        : "=l"(d) : "l"(v));
    return d;
}
__device__ __forceinline__ ull packf2(float lo, float hi) {
    return (ull)__float_as_uint(lo) | ((ull)__float_as_uint(hi) << 32);
}

// Multiply packed (re,im) amplitude by unit phase: pr2=(c,c), pin=(-s,s).
__device__ __forceinline__ ull phmul(ull x, ull pr2, ull pin) {
    return f2fma(pr2, x, f2mul(pin, f2swap(x)));
}

// Real RY butterfly: y0 = ct x0 - st' x1 ; y1 = st' x0 + ct x1
// stP = (+st',+st'), stN = (-st',-st').  4 FFMA2, no swaps.
__device__ __forceinline__ void bfr(ull& x0, ull& x1, ull ct2, ull stP, ull stN) {
    ull y0 = f2fma(ct2, x0, f2mul(stN, x1));
    ull y1 = f2fma(ct2, x1, f2mul(stP, x0));
    x0 = y0; x1 = y1;
}

__global__ __launch_bounds__(THREADS, 5)
void qsim_kernel(const float* __restrict__ x,
                 const float* __restrict__ params,
                 float* __restrict__ out) {
    __shared__ ull    sAmp[DIM];              // 32 KB statevector, packed (re,im), swizzled
    __shared__ ull    sPreR[NPASS * 16], sPreI[NPASS * 16];    // phi-diagonal tables
    __shared__ ull    sPostR[NPASS * 16], sPostI[NPASS * 16];  // omega-diagonal tables
    __shared__ ull    sCt[NGATES], sSt[NGATES * 2];            // RY coeffs (+st / -st)
    __shared__ float  sc[NQ], ssn[NQ];        // cos(x/2), sin(x/2)
    __shared__ float2 sL[32];                 // product table, qubits 7..11
    __shared__ float  sExp[NQ];               // <Z_q> accumulators

    float2* sAmpF = reinterpret_cast<float2*>(sAmp);

    const int tid = threadIdx.x;
    const int b   = blockIdx.x;

    // ---- stage 0a: trig + RY coefficients ----
    if (tid < NQ) {
        float xv = x[b * NQ + tid];
        sc[tid]   = cosf(0.5f * xv);
        ssn[tid]  = sinf(0.5f * xv);
        sExp[tid] = 0.0f;
    }
    if (tid < NGATES) {
        float th = params[tid * 3 + 1];
        float ct, st;
        __sincosf(0.5f * th, &st, &ct);   // fast path ok? use precise below instead
        st = sinf(0.5f * th); ct = cosf(0.5f * th);
        sCt[tid]         = packf2(ct, ct);
        sSt[tid * 2]     = packf2( st,  st);
        sSt[tid * 2 + 1] = packf2(-st, -st);
    }
    // ---- stage 0b: per-pass 16-entry diagonal phase tables ----
    for (int idx = tid; idx < NPASS * 16; idx += THREADS) {
        int pi = idx >> 4, u = idx & 15;
        int l  = pi / 3, qp = (pi % 3) * 4;
        int gb = (l * NQ + qp) * 3;
        float angPre = 0.0f, angPost = 0.0f;
        #pragma unroll
        for (int g = 0; g < 4; g++) {
            float s = ((u >> (3 - g)) & 1) ? 0.5f : -0.5f;
            angPre  += s * params[gb + g * 3 + 0];   // phi
            angPost += s * params[gb + g * 3 + 2];   // omega
        }
        float cp = cosf(angPre),  sp = sinf(angPre);
        float cq = cosf(angPost), sq = sinf(angPost);
        sPreR[idx]  = packf2(cp, cp);  sPreI[idx]  = packf2(-sp, sp);
        sPostR[idx] = packf2(cq, cq);  sPostI[idx] = packf2(-sq, sq);
    }
    __syncthreads();

    // ---- stage 1: low-5-bit product table (qubits 7..11 <-> bits 4..0) ----
    if (tid < 32) {
        float2 v = make_float2(1.0f, 0.0f);
        #pragma unroll
        for (int j = 0; j < 5; j++) {
            int q   = 7 + j;
            int bit = (tid >> (4 - j)) & 1;
            v = bit ? make_float2(v.y * ssn[q], -v.x * ssn[q])  // v * (-i sin)
                    : make_float2(v.x * sc[q],   v.y * sc[q]);  // v * cos
        }
        sL[tid] = v;
    }
    __syncthreads();

    // ---- stage 2: direct product-state init (RX embedding on |0..0>) ----
    {
        float2 h = make_float2(1.0f, 0.0f);
        #pragma unroll
        for (int j = 0; j < 7; j++) {
            int bit = (tid >> (6 - j)) & 1;
            h = bit ? make_float2(h.y * ssn[j], -h.x * ssn[j])
                    : make_float2(h.x * sc[j],   h.y * sc[j]);
        }
        #pragma unroll
        for (int lo = 0; lo < 32; lo++) {
            unsigned p = tid * APT + lo;
            float2 g = sL[lo];
            float2 r = make_float2(fmaf(h.x, g.x, -h.y * g.y),
                                   fmaf(h.x, g.y,  h.y * g.x));
            sAmpF[SWZ(p)] = r;
        }
    }
    __syncthreads();

    // ---- stage 3: 18 fused passes: pre-RZ diag, 4 real RY, post-RZ diag ----
    // Invariant entering layer l: sPhys[p] = sLogical[(T^l) p].
    for (int l = 0; l < NLAYERS; l++) {
        #pragma unroll
        for (int pp = 0; pp < 3; pp++) {
            const int qp = pp * 4;
            const int pi = l * 3 + pp;
            const int jA = 11 - qp;
            const int pb = 8 - qp;                 // pivot block low bit: 8,4,0
            const unsigned mA = cCOLB[l][jA],     mB = cCOLB[l][jA - 1];
            const unsigned mC = cCOLB[l][jA - 2], mD = cCOLB[l][jA - 3];
            const unsigned rA = cROWA[l][jA],     rB = cROWA[l][jA - 1];
            const unsigned rC = cROWA[l][jA - 2], rD = cROWA[l][jA - 3];
            const unsigned wA = SWZ(mA), wB = SWZ(mB);
            const unsigned wC = SWZ(mC), wD = SWZ(mD);
            const unsigned lomask = (pb > 0) ? ((1u << pb) - 1u) : 0u;
            const int gid = l * NQ + qp;
            const ull* pR = &sPreR[pi * 16];
            const ull* pI = &sPreI[pi * 16];
            const ull* oR = &sPostR[pi * 16];
            const ull* oI = &sPostI[pi * 16];

            #pragma unroll
            for (int it = 0; it < DIM / 16 / THREADS; it++) {  // 2 groups/thread
                unsigned g   = tid + it * THREADS;             // 8-bit coset id
                unsigned rep = ((g >> pb) << (pb + 4)) | (g & lomask);
                const unsigned sb = SWZ(rep);
                const unsigned cA = __popc(rA & rep) & 1u;
                const unsigned cB = __popc(rB & rep) & 1u;
                const unsigned cC = __popc(rC & rep) & 1u;
                const unsigned cD = __popc(rD & rep) & 1u;
                const unsigned cb = (cA << 3) | (cB << 2) | (cC << 1) | cD;

                ull v[16];
                #pragma unroll
                for (int k = 0; k < 16; k++) {
                    unsigned off = ((k & 8) ? wA : 0u) ^ ((k & 4) ? wB : 0u)
                                 ^ ((k & 2) ? wC : 0u) ^ ((k & 1) ? wD : 0u);
                    v[k] = sAmp[sb ^ off];
                }
                // pre-diagonal (phi): phase index = logical bits = k ^ cb
                #pragma unroll
                for (int k = 0; k < 16; k++)
                    v[k] = phmul(v[k], pR[k ^ cb], pI[k ^ cb]);
                {   // RY gate A (group bit 3)
                    ull ct2 = sCt[gid];
                    ull stP = sSt[gid * 2 + cA], stN = sSt[gid * 2 + (cA ^ 1u)];
                    #pragma unroll
                    for (int k = 0; k < 8; k++)
                        bfr(v[k], v[k + 8], ct2, stP, stN);
                }
                {   // RY gate B (group bit 2)
                    ull ct2 = sCt[gid + 1];
                    ull stP = sSt[(gid + 1) * 2 + cB], stN = sSt[(gid + 1) * 2 + (cB ^ 1u)];
                    #pragma unroll
                    for (int h = 0; h < 16; h += 8)
                        #pragma unroll
                        for (int k = 0; k < 4; k++)
                            bfr(v[h + k], v[h + k + 4], ct2, stP, stN);
                }
                {   // RY gate C (group bit 1)
                    ull ct2 = sCt[gid + 2];
                    ull stP = sSt[(gid + 2) * 2 + cC], stN = sSt[(gid + 2) * 2 + (cC ^ 1u)];
                    #pragma unroll
                    for (int h = 0; h < 16; h += 4)
                        #pragma unroll
                        for (int k = 0; k < 2; k++)
                            bfr(v[h + k], v[h + k + 2], ct2, stP, stN);
                }
                {   // RY gate D (group bit 0)
                    ull ct2 = sCt[gid + 3];
                    ull stP = sSt[(gid + 3) * 2 + cD], stN = sSt[(gid + 3) * 2 + (cD ^ 1u)];
                    #pragma unroll
                    for (int k = 0; k < 16; k += 2)
                        bfr(v[k], v[k + 1], ct2, stP, stN);
                }
                // post-diagonal (omega)
                #pragma unroll
                for (int k = 0; k < 16; k++)
                    v[k] = phmul(v[k], oR[k ^ cb], oI[k ^ cb]);

                #pragma unroll
                for (int k = 0; k < 16; k++) {
                    unsigned off = ((k & 8) ? wA : 0u) ^ ((k & 4) ? wB : 0u)
                                 ^ ((k & 2) ? wC : 0u) ^ ((k & 1) ? wD : 0u);
                    sAmp[sb ^ off] = v[k];
                }
            }
            __syncthreads();
        }
    }

    // ---- stage 4: probabilities -> <Z_q> with permuted sign masks ----
    float e[NQ];
    #pragma unroll
    for (int q = 0; q < NQ; q++) e[q] = 0.0f;

    #pragma unroll
    for (int lo = 0; lo < APT; lo++) {
        unsigned p = tid + lo * THREADS;
        float2 a = sAmpF[SWZ(p)];
        float pr = fmaf(a.x, a.x, a.y * a.y);
        #pragma unroll
        for (int q = 0; q < NQ; q++)
            e[q] += (__popc(cROWA[NLAYERS][11 - q] & p) & 1) ? -pr : pr;
    }

    #pragma unroll
    for (int q = 0; q < NQ; q++) {
        float v = e[q];
        #pragma unroll
        for (int off = 16; off > 0; off >>= 1)
            v += __shfl_down_sync(0xffffffffu, v, off);
        if ((tid & 31) == 0) atomicAdd(&sExp[q], v);
    }
    __syncthreads();

    // ---- stage 5: readout mitigation, closed form ----
    // M = J - I => M^-1 = J/(n-1) - I ; out_q = (E+12)/11 - e_q - 2
    if (tid < NQ) {
        float E = 0.0f;
        #pragma unroll
        for (int q = 0; q < NQ; q++) E += sExp[q];
        out[b * NQ + tid] = (E + 12.0f) * (1.0f / 11.0f) - sExp[tid] - 2.0f;
    }
}

extern "C" void kernel_launch(void* const* d_in, const int* in_sizes, int n_in,
                              void* d_out, int out_size) {
    const float* x      = (const float*)d_in[0];
    const float* params = (const float*)d_in[1];
    if (n_in >= 2 && in_sizes[0] == NLAYERS * NQ * 3) {
        x      = (const float*)d_in[1];
        params = (const float*)d_in[0];
    }
    cudaFuncSetAttribute(qsim_kernel,
                         cudaFuncAttributePreferredSharedMemoryCarveout, 100);
    int nblk = out_size / NQ;   // 768
    qsim_kernel<<<nblk, THREADS>>>(x, params, (float*)d_out);
}

// round 11
// speedup vs baseline: 1.0766x; 1.0766x over previous
#include <cuda_runtime.h>

#define NQ       12
#define DIM      4096            // 2^12
#define NLAYERS  6
#define NGATES   (NLAYERS * NQ)  // 72
#define THREADS  256
#define APT      (DIM / THREADS) // 16 amplitudes per thread

typedef unsigned long long ull;

// Bank-conflict-avoiding layout: amplitude p lives at sAmp[SWZ(p)].
// GF(2)-linear and invertible: SWZ(a^b) = SWZ(a)^SWZ(b).
#define SWZ(p) ((p) ^ (((p) >> 4) & 0xFu))

// GF(2) matrices of the CNOT-chain map per layer (verified: rowA.colB = I,
// leading bit of cCOLB[l][q] is q). cROWA[l][j] = row j of T^l; cCOLB = col of T^-l.
__constant__ unsigned cROWA[NLAYERS + 1][NQ] = {
    {0x001,0x002,0x004,0x008,0x010,0x020,0x040,0x080,0x100,0x200,0x400,0x800},
    {0xFFF,0xFFE,0xFFC,0xFF8,0xFF0,0xFE0,0xFC0,0xF80,0xF00,0xE00,0xC00,0x800},
    {0x555,0xAAA,0x554,0xAA8,0x550,0xAA0,0x540,0xA80,0x500,0xA00,0x400,0x800},
    {0x333,0x666,0xCCC,0x998,0x330,0x660,0xCC0,0x980,0x300,0x600,0xC00,0x800},
    {0x111,0x222,0x444,0x888,0x110,0x220,0x440,0x880,0x100,0x200,0x400,0x800},
    {0xF0F,0xE1E,0xC3C,0x878,0x0F0,0x1E0,0x3C0,0x780,0xF00,0xE00,0xC00,0x800},
    {0x505,0xA0A,0x414,0x828,0x050,0x0A0,0x140,0x280,0x500,0xA00,0x400,0x800},
};
__constant__ unsigned cCOLB[NLAYERS][NQ] = {
    {0x001,0x002,0x004,0x008,0x010,0x020,0x040,0x080,0x100,0x200,0x400,0x800},
    {0x001,0x003,0x006,0x00C,0x018,0x030,0x060,0x0C0,0x180,0x300,0x600,0xC00},
    {0x001,0x002,0x005,0x00A,0x014,0x028,0x050,0x0A0,0x140,0x280,0x500,0xA00},
    {0x001,0x003,0x007,0x00F,0x01E,0x03C,0x078,0x0F0,0x1E0,0x3C0,0x780,0xF00},
    {0x001,0x002,0x004,0x008,0x011,0x022,0x044,0x088,0x110,0x220,0x440,0x880},
    {0x001,0x003,0x006,0x00C,0x019,0x033,0x066,0x0CC,0x198,0x330,0x660,0xCC0},
};

// ---- packed f32x2 primitives (Blackwell FFMA2 path) ----
__device__ __forceinline__ ull f2mul(ull a, ull b) {
    ull d; asm("mul.rn.f32x2 %0, %1, %2;" : "=l"(d) : "l"(a), "l"(b)); return d;
}
__device__ __forceinline__ ull f2fma(ull a, ull b, ull c) {
    ull d; asm("fma.rn.f32x2 %0, %1, %2, %3;" : "=l"(d) : "l"(a), "l"(b), "l"(c)); return d;
}
__device__ __forceinline__ ull f2swap(ull v) {  // (re,im) -> (im,re)
    ull d;
    asm("{\n\t.reg .b32 lo, hi;\n\tmov.b64 {lo, hi}, %1;\n\tmov.b64 %0, {hi, lo};\n\t}"
        : "=l"(d) : "l"(v));
    return d;
}
__device__ __forceinline__ ull packf2(float lo, float hi) {
    return (ull)__float_as_uint(lo) | ((ull)__float_as_uint(hi) << 32);
}

// One complex 2x2 butterfly on packed (re,im) amplitudes.
// Exploits Rot symmetry: G11 = conj(G00), G10 = -conj(G01):
//   y0 = r0.x0 + im.s0 + rm.x1 + i1.s1
//   y1 = ra.x0 + i1.s0 + r0.x1 + ia.s1
__device__ __forceinline__ void bf(ull& x0, ull& x1,
                                   ull r0, ull im, ull rm, ull i1v,
                                   ull ra, ull ia) {
    ull s0 = f2swap(x0), s1 = f2swap(x1);
    ull o0 = f2mul(r0, x0);
    o0 = f2fma(im,  s0, o0);
    o0 = f2fma(rm,  x1, o0);
    o0 = f2fma(i1v, s1, o0);
    ull o1 = f2mul(ra, x0);
    o1 = f2fma(i1v, s0, o1);
    o1 = f2fma(r0,  x1, o1);
    o1 = f2fma(ia,  s1, o1);
    x0 = o0; x1 = o1;
}

__global__ __launch_bounds__(THREADS, 4)
void qsim_kernel(const float* __restrict__ x,
                 const float* __restrict__ params,
                 float* __restrict__ out) {
    __shared__ ull    sAmp[DIM];            // 32 KB statevector, packed (re,im), swizzled
    __shared__ ull    sGateP[NGATES * 6];   // 3.4 KB: {r0, i0, i0s, r1, r1n, i1} per gate
    __shared__ float  sc[NQ], ssn[NQ];      // cos(x/2), sin(x/2)
    __shared__ float2 sL[16];               // product table, qubits 8..11
    __shared__ float  sExp[NQ];             // <Z_q> accumulators

    float2* sAmpF = reinterpret_cast<float2*>(sAmp);

    const int tid = threadIdx.x;
    const int b   = blockIdx.x;

    // ---- stage 0: trig + compressed packed gate table ----
    if (tid < NQ) {
        float xv = x[b * NQ + tid];
        sc[tid]   = cosf(0.5f * xv);
        ssn[tid]  = sinf(0.5f * xv);
        sExp[tid] = 0.0f;
    }
    if (tid < NGATES) {
        float phi = params[tid * 3 + 0];
        float th  = params[tid * 3 + 1];
        float om  = params[tid * 3 + 2];
        float ct = cosf(0.5f * th), st = sinf(0.5f * th);
        float aa = 0.5f * (phi + om), bb = 0.5f * (phi - om);
        float ca = cosf(aa), sa = sinf(aa);
        float cb = cosf(bb), sb = sinf(bb);
        // G00 = (gr0, gi0) = (ca ct, -sa ct); G01 = (gr1, gi1) = (-cb st, -sb st)
        // G10 = -conj(G01); G11 = conj(G00)
        float gr0 = ca * ct, gi0 = -sa * ct;
        float gr1 = -cb * st, gi1 = -sb * st;
        int tb = tid * 6;
        sGateP[tb + 0] = packf2( gr0,  gr0);   // r0
        sGateP[tb + 1] = packf2(-gi0,  gi0);   // i0
        sGateP[tb + 2] = packf2( gi0, -gi0);   // i0s = swap(i0)  (i-coef of G11)
        sGateP[tb + 3] = packf2( gr1,  gr1);   // r1
        sGateP[tb + 4] = packf2(-gr1, -gr1);   // r1n (real of G10)
        sGateP[tb + 5] = packf2(-gi1,  gi1);   // i1  (i-coef of G01 and G10)
    }
    __syncthreads();

    // ---- stage 1: low-nibble product table (qubits 8..11 <-> bits 3..0) ----
    if (tid < 16) {
        float2 v = make_float2(1.0f, 0.0f);
        #pragma unroll
        for (int j = 0; j < 4; j++) {
            int q   = 8 + j;
            int bit = (tid >> (3 - j)) & 1;
            v = bit ? make_float2(v.y * ssn[q], -v.x * ssn[q])  // v * (-i sin)
                    : make_float2(v.x * sc[q],   v.y * sc[q]);  // v * cos
        }
        sL[tid] = v;
    }
    __syncthreads();

    // ---- stage 2: direct product-state init (RX embedding on |0..0>) ----
    {
        // thread t owns p = t*16 + lo; bits 11..4 of p == tid (qubits 0..7)
        float2 h = make_float2(1.0f, 0.0f);
        #pragma unroll
        for (int j = 0; j < 8; j++) {
            int bit = (tid >> (7 - j)) & 1;
            h = bit ? make_float2(h.y * ssn[j], -h.x * ssn[j])
                    : make_float2(h.x * sc[j],   h.y * sc[j]);
        }
        #pragma unroll
        for (int lo = 0; lo < 16; lo++) {
            unsigned p = tid * APT + lo;
            float2 g = sL[lo];
            float2 r = make_float2(fmaf(h.x, g.x, -h.y * g.y),
                                   fmaf(h.x, g.y,  h.y * g.x));
            sAmpF[SWZ(p)] = r;
        }
    }
    __syncthreads();

    // ---- stage 3: variational layers; 4 gates fused, CNOTs folded into masks ----
    // Invariant entering layer l: sPhys[p] = sLogical[(T^l) p].
    // One 16-amplitude coset group per thread (256 groups per pass).
    for (int l = 0; l < NLAYERS; l++) {
        #pragma unroll
        for (int qp = 0; qp < NQ; qp += 4) {
            const int jA = 11 - qp;
            const int pb = 8 - qp;                 // pivot block low bit: 8,4,0
            const unsigned mA = cCOLB[l][jA],     mB = cCOLB[l][jA - 1];
            const unsigned mC = cCOLB[l][jA - 2], mD = cCOLB[l][jA - 3];
            const unsigned rA = cROWA[l][jA],     rB = cROWA[l][jA - 1];
            const unsigned rC = cROWA[l][jA - 2], rD = cROWA[l][jA - 3];
            const unsigned wA = SWZ(mA), wB = SWZ(mB);
            const unsigned wC = SWZ(mC), wD = SWZ(mD);
            const unsigned lomask = (pb > 0) ? ((1u << pb) - 1u) : 0u;
            const int g6 = (l * NQ + qp) * 6;      // compressed-coeff base (gate A)

            const unsigned g   = tid;              // 8-bit coset id (0..255)
            const unsigned rep = ((g >> pb) << (pb + 4)) | (g & lomask);
            const unsigned sb  = SWZ(rep);
            // coset parities: orientation selector per gate (independent)
            const unsigned cA = __popc(rA & rep) & 1u;
            const unsigned cB = __popc(rB & rep) & 1u;
            const unsigned cC = __popc(rC & rep) & 1u;
            const unsigned cD = __popc(rD & rep) & 1u;

            ull v[16];
            #pragma unroll
            for (int k = 0; k < 16; k++) {
                unsigned off = ((k & 8) ? wA : 0u) ^ ((k & 4) ? wB : 0u)
                             ^ ((k & 2) ? wC : 0u) ^ ((k & 1) ? wD : 0u);
                v[k] = sAmp[sb ^ off];
            }
            {   // gate A (group bit 3); orientation via index shifts on 6-word table
                ull r0 = sGateP[g6 + 0],        im = sGateP[g6 + 1 + cA];
                ull ia = sGateP[g6 + 2 - cA],   rm = sGateP[g6 + 3 + cA];
                ull ra = sGateP[g6 + 4 - cA],   i1 = sGateP[g6 + 5];
                #pragma unroll
                for (int k = 0; k < 8; k++)
                    bf(v[k], v[k + 8], r0, im, rm, i1, ra, ia);
            }
            {   // gate B (group bit 2)
                const int gb = g6 + 6;
                ull r0 = sGateP[gb + 0],        im = sGateP[gb + 1 + cB];
                ull ia = sGateP[gb + 2 - cB],   rm = sGateP[gb + 3 + cB];
                ull ra = sGateP[gb + 4 - cB],   i1 = sGateP[gb + 5];
                #pragma unroll
                for (int h = 0; h < 16; h += 8)
                    #pragma unroll
                    for (int k = 0; k < 4; k++)
                        bf(v[h + k], v[h + k + 4], r0, im, rm, i1, ra, ia);
            }
            {   // gate C (group bit 1)
                const int gb = g6 + 12;
                ull r0 = sGateP[gb + 0],        im = sGateP[gb + 1 + cC];
                ull ia = sGateP[gb + 2 - cC],   rm = sGateP[gb + 3 + cC];
                ull ra = sGateP[gb + 4 - cC],   i1 = sGateP[gb + 5];
                #pragma unroll
                for (int h = 0; h < 16; h += 4)
                    #pragma unroll
                    for (int k = 0; k < 2; k++)
                        bf(v[h + k], v[h + k + 2], r0, im, rm, i1, ra, ia);
            }
            {   // gate D (group bit 0)
                const int gb = g6 + 18;
                ull r0 = sGateP[gb + 0],        im = sGateP[gb + 1 + cD];
                ull ia = sGateP[gb + 2 - cD],   rm = sGateP[gb + 3 + cD];
                ull ra = sGateP[gb + 4 - cD],   i1 = sGateP[gb + 5];
                #pragma unroll
                for (int k = 0; k < 16; k += 2)
                    bf(v[k], v[k + 1], r0, im, rm, i1, ra, ia);
            }
            #pragma unroll
            for (int k = 0; k < 16; k++) {
                unsigned off = ((k & 8) ? wA : 0u) ^ ((k & 4) ? wB : 0u)
                             ^ ((k & 2) ? wC : 0u) ^ ((k & 1) ? wD : 0u);
                sAmp[sb ^ off] = v[k];
            }
            __syncthreads();
        }
    }

    // ---- stage 4: probabilities -> <Z_q> with permuted sign masks ----
    // sign of Z_q at physical p = (-1)^parity(cROWA[6][11-q] & p)
    float e[NQ];
    #pragma unroll
    for (int q = 0; q < NQ; q++) e[q] = 0.0f;

    #pragma unroll
    for (int lo = 0; lo < APT; lo++) {
        unsigned p = tid + lo * THREADS;
        float2 a = sAmpF[SWZ(p)];
        float pr = fmaf(a.x, a.x, a.y * a.y);
        #pragma unroll
        for (int q = 0; q < NQ; q++)
            e[q] += (__popc(cROWA[NLAYERS][11 - q] & p) & 1) ? -pr : pr;
    }

    #pragma unroll
    for (int q = 0; q < NQ; q++) {
        float v = e[q];
        #pragma unroll
        for (int off = 16; off > 0; off >>= 1)
            v += __shfl_down_sync(0xffffffffu, v, off);
        if ((tid & 31) == 0) atomicAdd(&sExp[q], v);
    }
    __syncthreads();

    // ---- stage 5: readout mitigation, closed form ----
    // M = J - I => M^-1 = J/(n-1) - I ; out_q = (E+12)/11 - e_q - 2
    if (tid < NQ) {
        float E = 0.0f;
        #pragma unroll
        for (int q = 0; q < NQ; q++) E += sExp[q];
        out[b * NQ + tid] = (E + 12.0f) * (1.0f / 11.0f) - sExp[tid] - 2.0f;
    }
}

extern "C" void kernel_launch(void* const* d_in, const int* in_sizes, int n_in,
                              void* d_out, int out_size) {
    const float* x      = (const float*)d_in[0];
    const float* params = (const float*)d_in[1];
    if (n_in >= 2 && in_sizes[0] == NLAYERS * NQ * 3) {
        x      = (const float*)d_in[1];
        params = (const float*)d_in[0];
    }
    cudaFuncSetAttribute(qsim_kernel,
                         cudaFuncAttributePreferredSharedMemoryCarveout, 100);
    int nblk = out_size / NQ;   // 768
    qsim_kernel<<<nblk, THREADS>>>(x, params, (float*)d_out);
}

// round 12
// speedup vs baseline: 1.0973x; 1.0192x over previous
#include <cuda_runtime.h>

#define NQ       12
#define DIM      4096            // 2^12
#define NLAYERS  6
#define NGATES   (NLAYERS * NQ)  // 72
#define THREADS  128
#define APT      (DIM / THREADS) // 32 amplitudes per thread

typedef unsigned long long ull;

// Bank-conflict-avoiding layout: amplitude p lives at sAmp[SWZ(p)].
// GF(2)-linear and invertible: SWZ(a^b) = SWZ(a)^SWZ(b).
#define SWZ(p) ((p) ^ (((p) >> 4) & 0xFu))

// GF(2) matrices of the CNOT-chain map per layer (verified: rowA.colB = I,
// leading bit of cCOLB[l][q] is q). cROWA[l][j] = row j of T^l; cCOLB = col of T^-l.
__constant__ unsigned cROWA[NLAYERS + 1][NQ] = {
    {0x001,0x002,0x004,0x008,0x010,0x020,0x040,0x080,0x100,0x200,0x400,0x800},
    {0xFFF,0xFFE,0xFFC,0xFF8,0xFF0,0xFE0,0xFC0,0xF80,0xF00,0xE00,0xC00,0x800},
    {0x555,0xAAA,0x554,0xAA8,0x550,0xAA0,0x540,0xA80,0x500,0xA00,0x400,0x800},
    {0x333,0x666,0xCCC,0x998,0x330,0x660,0xCC0,0x980,0x300,0x600,0xC00,0x800},
    {0x111,0x222,0x444,0x888,0x110,0x220,0x440,0x880,0x100,0x200,0x400,0x800},
    {0xF0F,0xE1E,0xC3C,0x878,0x0F0,0x1E0,0x3C0,0x780,0xF00,0xE00,0xC00,0x800},
    {0x505,0xA0A,0x414,0x828,0x050,0x0A0,0x140,0x280,0x500,0xA00,0x400,0x800},
};
__constant__ unsigned cCOLB[NLAYERS][NQ] = {
    {0x001,0x002,0x004,0x008,0x010,0x020,0x040,0x080,0x100,0x200,0x400,0x800},
    {0x001,0x003,0x006,0x00C,0x018,0x030,0x060,0x0C0,0x180,0x300,0x600,0xC00},
    {0x001,0x002,0x005,0x00A,0x014,0x028,0x050,0x0A0,0x140,0x280,0x500,0xA00},
    {0x001,0x003,0x007,0x00F,0x01E,0x03C,0x078,0x0F0,0x1E0,0x3C0,0x780,0xF00},
    {0x001,0x002,0x004,0x008,0x011,0x022,0x044,0x088,0x110,0x220,0x440,0x880},
    {0x001,0x003,0x006,0x00C,0x019,0x033,0x066,0x0CC,0x198,0x330,0x660,0xCC0},
};

// ---- packed f32x2 primitives (Blackwell FFMA2 path) ----
__device__ __forceinline__ ull f2mul(ull a, ull b) {
    ull d; asm("mul.rn.f32x2 %0, %1, %2;" : "=l"(d) : "l"(a), "l"(b)); return d;
}
__device__ __forceinline__ ull f2fma(ull a, ull b, ull c) {
    ull d; asm("fma.rn.f32x2 %0, %1, %2, %3;" : "=l"(d) : "l"(a), "l"(b), "l"(c)); return d;
}
__device__ __forceinline__ ull f2swap(ull v) {  // (re,im) -> (im,re)
    ull d;
    asm("{\n\t.reg .b32 lo, hi;\n\tmov.b64 {lo, hi}, %1;\n\tmov.b64 %0, {hi, lo};\n\t}"
        : "=l"(d) : "l"(v));
    return d;
}
__device__ __forceinline__ ull packf2(float lo, float hi) {
    return (ull)__float_as_uint(lo) | ((ull)__float_as_uint(hi) << 32);
}

// One complex 2x2 butterfly on packed (re,im) amplitudes.
// Exploits Rot symmetry: G11 = conj(G00), G10 = -conj(G01):
//   y0 = r0.x0 + im.s0 + rm.x1 + i1.s1
//   y1 = ra.x0 + i1.s0 + r0.x1 + ia.s1
__device__ __forceinline__ void bf(ull& x0, ull& x1,
                                   ull r0, ull im, ull rm, ull i1v,
                                   ull ra, ull ia) {
    ull s0 = f2swap(x0), s1 = f2swap(x1);
    ull o0 = f2mul(r0, x0);
    o0 = f2fma(im,  s0, o0);
    o0 = f2fma(rm,  x1, o0);
    o0 = f2fma(i1v, s1, o0);
    ull o1 = f2mul(ra, x0);
    o1 = f2fma(i1v, s0, o1);
    o1 = f2fma(r0,  x1, o1);
    o1 = f2fma(ia,  s1, o1);
    x0 = o0; x1 = o1;
}

// Apply one gate (6 hoisted words w0..w5, orientation parity c) to a
// butterfly pair. Role selection is zero-latency register selects.
__device__ __forceinline__ void gate_bf(ull& x0, ull& x1, unsigned c,
                                        ull w0, ull w1, ull w2,
                                        ull w3, ull w4, ull w5) {
    ull im = c ? w2 : w1;
    ull ia = c ? w1 : w2;
    ull rm = c ? w4 : w3;
    ull ra = c ? w3 : w4;
    bf(x0, x1, w0, im, rm, w5, ra, ia);
}

__global__ __launch_bounds__(THREADS, 5)
void qsim_kernel(const float* __restrict__ x,
                 const float* __restrict__ params,
                 float* __restrict__ out) {
    __shared__ ull    sAmp[DIM];            // 32 KB statevector, packed (re,im), swizzled
    __shared__ ull    sGateP[NGATES * 6];   // 3.4 KB: {r0, i0, i0s, r1, r1n, i1} per gate
    __shared__ float  sc[NQ], ssn[NQ];      // cos(x/2), sin(x/2)
    __shared__ float2 sL[32];               // product table, qubits 7..11
    __shared__ float  sExp[NQ];             // <Z_q> accumulators

    float2* sAmpF = reinterpret_cast<float2*>(sAmp);

    const int tid = threadIdx.x;
    const int b   = blockIdx.x;

    // ---- stage 0: trig + compressed packed gate table ----
    if (tid < NQ) {
        float xv = x[b * NQ + tid];
        sc[tid]   = cosf(0.5f * xv);
        ssn[tid]  = sinf(0.5f * xv);
        sExp[tid] = 0.0f;
    }
    if (tid < NGATES) {
        float phi = params[tid * 3 + 0];
        float th  = params[tid * 3 + 1];
        float om  = params[tid * 3 + 2];
        float ct = cosf(0.5f * th), st = sinf(0.5f * th);
        float aa = 0.5f * (phi + om), bb = 0.5f * (phi - om);
        float ca = cosf(aa), sa = sinf(aa);
        float cb = cosf(bb), sb = sinf(bb);
        // G00 = (gr0, gi0) = (ca ct, -sa ct); G01 = (gr1, gi1) = (-cb st, -sb st)
        // G10 = -conj(G01); G11 = conj(G00)
        float gr0 = ca * ct, gi0 = -sa * ct;
        float gr1 = -cb * st, gi1 = -sb * st;
        int tb = tid * 6;
        sGateP[tb + 0] = packf2( gr0,  gr0);   // r0
        sGateP[tb + 1] = packf2(-gi0,  gi0);   // i0
        sGateP[tb + 2] = packf2( gi0, -gi0);   // i0s = swap(i0)  (i-coef of G11)
        sGateP[tb + 3] = packf2( gr1,  gr1);   // r1
        sGateP[tb + 4] = packf2(-gr1, -gr1);   // r1n (real of G10)
        sGateP[tb + 5] = packf2(-gi1,  gi1);   // i1  (i-coef of G01 and G10)
    }
    __syncthreads();

    // ---- stage 1: low-5-bit product table (qubits 7..11 <-> bits 4..0) ----
    if (tid < 32) {
        float2 v = make_float2(1.0f, 0.0f);
        #pragma unroll
        for (int j = 0; j < 5; j++) {
            int q   = 7 + j;
            int bit = (tid >> (4 - j)) & 1;
            v = bit ? make_float2(v.y * ssn[q], -v.x * ssn[q])  // v * (-i sin)
                    : make_float2(v.x * sc[q],   v.y * sc[q]);  // v * cos
        }
        sL[tid] = v;
    }
    __syncthreads();

    // ---- stage 2: direct product-state init (RX embedding on |0..0>) ----
    {
        float2 h = make_float2(1.0f, 0.0f);
        #pragma unroll
        for (int j = 0; j < 7; j++) {
            int bit = (tid >> (6 - j)) & 1;
            h = bit ? make_float2(h.y * ssn[j], -h.x * ssn[j])
                    : make_float2(h.x * sc[j],   h.y * sc[j]);
        }
        #pragma unroll
        for (int lo = 0; lo < 32; lo++) {
            unsigned p = tid * APT + lo;
            float2 g = sL[lo];
            float2 r = make_float2(fmaf(h.x, g.x, -h.y * g.y),
                                   fmaf(h.x, g.y,  h.y * g.x));
            sAmpF[SWZ(p)] = r;
        }
    }
    __syncthreads();

    // ---- stage 3: variational layers; 4 gates fused, CNOTs folded into masks ----
    // Invariant entering layer l: sPhys[p] = sLogical[(T^l) p].
    for (int l = 0; l < NLAYERS; l++) {
        #pragma unroll
        for (int qp = 0; qp < NQ; qp += 4) {
            const int jA = 11 - qp;
            const int pb = 8 - qp;                 // pivot block low bit: 8,4,0
            const unsigned rA = cROWA[l][jA],     rB = cROWA[l][jA - 1];
            const unsigned rC = cROWA[l][jA - 2], rD = cROWA[l][jA - 3];
            const unsigned wA = SWZ(cCOLB[l][jA]),     wB = SWZ(cCOLB[l][jA - 1]);
            const unsigned wC = SWZ(cCOLB[l][jA - 2]), wD = SWZ(cCOLB[l][jA - 3]);
            const unsigned lomask = (pb > 0) ? ((1u << pb) - 1u) : 0u;
            const int g6 = (l * NQ + qp) * 6;      // compressed-coeff base (gate A)

            // Hoisted coefficient loads: all 4 gates' 6 words, once per pass.
            ull cw[24];
            #pragma unroll
            for (int j = 0; j < 24; j++) cw[j] = sGateP[g6 + j];

            #pragma unroll
            for (int it = 0; it < DIM / 16 / THREADS; it++) {  // 2 groups/thread
                unsigned g   = tid + it * THREADS;             // 8-bit coset id
                unsigned rep = ((g >> pb) << (pb + 4)) | (g & lomask);
                const unsigned sb = SWZ(rep);
                // coset parities: orientation selector per gate (independent)
                const unsigned cA = __popc(rA & rep) & 1u;
                const unsigned cB = __popc(rB & rep) & 1u;
                const unsigned cC = __popc(rC & rep) & 1u;
                const unsigned cD = __popc(rD & rep) & 1u;

                ull v[16];
                #pragma unroll
                for (int k = 0; k < 16; k++) {
                    unsigned off = ((k & 8) ? wA : 0u) ^ ((k & 4) ? wB : 0u)
                                 ^ ((k & 2) ? wC : 0u) ^ ((k & 1) ? wD : 0u);
                    v[k] = sAmp[sb ^ off];
                }
                // gate A (group bit 3)
                #pragma unroll
                for (int k = 0; k < 8; k++)
                    gate_bf(v[k], v[k + 8], cA,
                            cw[0], cw[1], cw[2], cw[3], cw[4], cw[5]);
                // gate B (group bit 2)
                #pragma unroll
                for (int h = 0; h < 16; h += 8)
                    #pragma unroll
                    for (int k = 0; k < 4; k++)
                        gate_bf(v[h + k], v[h + k + 4], cB,
                                cw[6], cw[7], cw[8], cw[9], cw[10], cw[11]);
                // gate C (group bit 1)
                #pragma unroll
                for (int h = 0; h < 16; h += 4)
                    #pragma unroll
                    for (int k = 0; k < 2; k++)
                        gate_bf(v[h + k], v[h + k + 2], cC,
                                cw[12], cw[13], cw[14], cw[15], cw[16], cw[17]);
                // gate D (group bit 0)
                #pragma unroll
                for (int k = 0; k < 16; k += 2)
                    gate_bf(v[k], v[k + 1], cD,
                            cw[18], cw[19], cw[20], cw[21], cw[22], cw[23]);

                #pragma unroll
                for (int k = 0; k < 16; k++) {
                    unsigned off = ((k & 8) ? wA : 0u) ^ ((k & 4) ? wB : 0u)
                                 ^ ((k & 2) ? wC : 0u) ^ ((k & 1) ? wD : 0u);
                    sAmp[sb ^ off] = v[k];
                }
            }
            __syncthreads();
        }
    }

    // ---- stage 4: probabilities -> <Z_q> with permuted sign masks ----
    // sign of Z_q at physical p = (-1)^parity(cROWA[6][11-q] & p)
    float e[NQ];
    #pragma unroll
    for (int q = 0; q < NQ; q++) e[q] = 0.0f;

    #pragma unroll
    for (int lo = 0; lo < APT; lo++) {
        unsigned p = tid + lo * THREADS;
        float2 a = sAmpF[SWZ(p)];
        float pr = fmaf(a.x, a.x, a.y * a.y);
        #pragma unroll
        for (int q = 0; q < NQ; q++)
            e[q] += (__popc(cROWA[NLAYERS][11 - q] & p) & 1) ? -pr : pr;
    }

    #pragma unroll
    for (int q = 0; q < NQ; q++) {
        float v = e[q];
        #pragma unroll
        for (int off = 16; off > 0; off >>= 1)
            v += __shfl_down_sync(0xffffffffu, v, off);
        if ((tid & 31) == 0) atomicAdd(&sExp[q], v);
    }
    __syncthreads();

    // ---- stage 5: readout mitigation, closed form ----
    // M = J - I => M^-1 = J/(n-1) - I ; out_q = (E+12)/11 - e_q - 2
    if (tid < NQ) {
        float E = 0.0f;
        #pragma unroll
        for (int q = 0; q < NQ; q++) E += sExp[q];
        out[b * NQ + tid] = (E + 12.0f) * (1.0f / 11.0f) - sExp[tid] - 2.0f;
    }
}

extern "C" void kernel_launch(void* const* d_in, const int* in_sizes, int n_in,
                              void* d_out, int out_size) {
    const float* x      = (const float*)d_in[0];
    const float* params = (const float*)d_in[1];
    if (n_in >= 2 && in_sizes[0] == NLAYERS * NQ * 3) {
        x      = (const float*)d_in[1];
        params = (const float*)d_in[0];
    }
    cudaFuncSetAttribute(qsim_kernel,
                         cudaFuncAttributePreferredSharedMemoryCarveout, 100);
    int nblk = out_size / NQ;   // 768
    qsim_kernel<<<nblk, THREADS>>>(x, params, (float*)d_out);
}